// round 17
// baseline (speedup 1.0000x reference)
#include <cuda_runtime.h>

// DigitCaps broadcasted batched matvec:
//   u_hat[b,r,c,o] = sum_i W[r,c,o,i] * x[b,r,i] + bias[o]
// B=512, R=1152, C=10, O=16, I=8, fp32.
//
// R15: R14 (65.6us champion) + full strength reduction of hot-loop
// addressing. Two hoisted 64-bit store base pointers make every store
// address "base + compile-time immediate" (k*2949120B + cp*128B, both
// within STG's +-8MB imm range), and the W smem row address becomes
// "wrb + cp*288 floats" (immediate LDS offsets). Removes ~40 IMADs/thread
// from the unrolled loop (alu pipe was 14.3%, issue 46.9%).
// All traffic terms identical to R14: coop x tile (one 128B line per b,
// read once chip-wide) -> prologue LDS -> regs; padded conflict-free smem
// W; o-row-major FMA chains (72 regs, 7 CTAs/SM); 4-segment STG.128.
// Lane = bg(4) x c2(2) x o4(4); warp w = r_local. 4 b's x 2 c's x 4 o's/thr.

#define DC_B 512
#define DC_R 1152
#define DC_C 10
#define DC_O 16
#define DC_I 8

#define RB 4     // r rows per block (one per warp)
#define BT 16    // batch elems per block
// smem W: 4r * 10c * 4(o4) rows of 36 floats = 5760 floats (23KB)
// smem x: 16 b * 36 floats (32 data + 4 pad)  =  576 floats (2.3KB)
#define SW_FLOATS 5760
#define SX_FLOATS 576
#define SMEM_BYTES ((SW_FLOATS + SX_FLOATS) * 4)

#define OUT_B_STRIDE (DC_R * DC_C * DC_O)    // 184320 floats per b
#define OUT_K_STRIDE (4 * OUT_B_STRIDE)      // 737280 floats per k step

// One o-row FMA chain: component 'comp' of acc for W row pair (wa, wb).
#define OROW_CHAIN(accv, comp, wa, wb, va, vb, biasv)                      \
    (accv).comp = fmaf((wa).x, (va).x, fmaf((wa).y, (va).y,                \
                  fmaf((wa).z, (va).z, fmaf((wa).w, (va).w,                \
                  fmaf((wb).x, (vb).x, fmaf((wb).y, (vb).y,                \
                  fmaf((wb).z, (vb).z, fmaf((wb).w, (vb).w, (biasv)))))))))

__global__ __launch_bounds__(128, 7)
void digitcaps_kernel(const float* __restrict__ x,
                      const float* __restrict__ W,
                      const float* __restrict__ bias,
                      float* __restrict__ out)
{
    extern __shared__ float smem[];
    float* sW = smem;                 // [g][36], g = (r_local*10 + c)*4 + o4
    float* sx = smem + SW_FLOATS;     // [b_local][36]: 4r x 8i + pad

    const unsigned tid = threadIdx.x;
    const unsigned r0  = blockIdx.x * RB;
    const unsigned b0  = blockIdx.y * BT;

    // ---- cooperative x load: 16 b, each b = exactly one 128B line (4r x 8i) ----
    {
        const unsigned b_i = tid >> 3;               // 0..15
        const unsigned m   = tid & 7u;               // float4 index within line
        const float4 v = *reinterpret_cast<const float4*>(
            x + ((b0 + b_i) * (unsigned)DC_R + r0) * (unsigned)DC_I + m * 4u);
        *reinterpret_cast<float4*>(sx + b_i * 36u + m * 4u) = v;
    }

    // ---- cooperative W load: 4 r rows * 1280 floats = 1280 float4, coalesced ----
    {
        const float4* Wg = reinterpret_cast<const float4*>(
            W + r0 * (unsigned)(DC_C * DC_O * DC_I));
#pragma unroll
        for (unsigned q4 = 0; q4 < 10; ++q4) {
            const unsigned q = q4 * 128u + tid;      // float4 index in W tile
            const float4 v = Wg[q];
            // q -> (rc, o, ih): flat = ((rc)*16 + o)*2 + ih
            const unsigned ih = q & 1u;
            const unsigned o  = (q >> 1) & 15u;
            const unsigned rc = q >> 5;              // r_local*10 + c
            const unsigned g  = rc * 4u + (o >> 2);
            *reinterpret_cast<float4*>(sW + g * 36u + (o & 3u) * 8u + ih * 4u) = v;
        }
    }

    const unsigned lane = tid & 31u;
    const unsigned w    = tid >> 5;      // warp id == r_local (0..3)
    const unsigned bg   = lane >> 3;     // 0..3 batch group
    const unsigned c2   = (lane >> 2) & 1u;
    const unsigned o4   = lane & 3u;

    const unsigned r = r0 + w;

    const float4 bb = *reinterpret_cast<const float4*>(bias + o4 * 4u);

    // ---- hoisted store bases: all per-(cp,k) offsets become immediates ----
    // element offset: ((b*R + r)*C + c)*O + o, b = b0 + k*4 + bg, c = cp*2+c2
    float* base01 = out + (b0 + bg) * (unsigned)OUT_B_STRIDE
                        + r * (unsigned)(DC_C * DC_O) + c2 * 16u + o4 * 4u;
    float* base23 = base01 + 2u * (unsigned)OUT_K_STRIDE;

    // ---- hoisted W smem row base: per-cp offset = cp*288 (immediate) ----
    // row addr = (w*40 + c*4 + o4)*36 = w*1440 + c2*144 + o4*36 + cp*288
    const float* wrb = sW + w * 1440u + c2 * 144u + o4 * 36u;

    __syncthreads();

    // ---- x to registers (PROLOGUE only): 8 LDS.128, 4 distinct addrs each ----
    float4 xa[4], xb[4];
#pragma unroll
    for (int k = 0; k < 4; ++k) {
        const unsigned bl = (unsigned)k * 4u + bg;
        xa[k] = *reinterpret_cast<const float4*>(sx + bl * 36u + w * 8u);
        xb[k] = *reinterpret_cast<const float4*>(sx + bl * 36u + w * 8u + 4u);
    }

#pragma unroll
    for (int cp = 0; cp < 5; ++cp) {
        const float* wr = wrb + cp * 288;            // immediate per cp

        float4 acc0, acc1, acc2, acc3;

        // o-row 0: only (wa, wb) live among W values
        {
            const float4 wa = *reinterpret_cast<const float4*>(wr + 0);
            const float4 wb = *reinterpret_cast<const float4*>(wr + 4);
            OROW_CHAIN(acc0, x, wa, wb, xa[0], xb[0], bb.x);
            OROW_CHAIN(acc1, x, wa, wb, xa[1], xb[1], bb.x);
            OROW_CHAIN(acc2, x, wa, wb, xa[2], xb[2], bb.x);
            OROW_CHAIN(acc3, x, wa, wb, xa[3], xb[3], bb.x);
        }
        // o-row 1
        {
            const float4 wa = *reinterpret_cast<const float4*>(wr + 8);
            const float4 wb = *reinterpret_cast<const float4*>(wr + 12);
            OROW_CHAIN(acc0, y, wa, wb, xa[0], xb[0], bb.y);
            OROW_CHAIN(acc1, y, wa, wb, xa[1], xb[1], bb.y);
            OROW_CHAIN(acc2, y, wa, wb, xa[2], xb[2], bb.y);
            OROW_CHAIN(acc3, y, wa, wb, xa[3], xb[3], bb.y);
        }
        // o-row 2
        {
            const float4 wa = *reinterpret_cast<const float4*>(wr + 16);
            const float4 wb = *reinterpret_cast<const float4*>(wr + 20);
            OROW_CHAIN(acc0, z, wa, wb, xa[0], xb[0], bb.z);
            OROW_CHAIN(acc1, z, wa, wb, xa[1], xb[1], bb.z);
            OROW_CHAIN(acc2, z, wa, wb, xa[2], xb[2], bb.z);
            OROW_CHAIN(acc3, z, wa, wb, xa[3], xb[3], bb.z);
        }
        // o-row 3
        {
            const float4 wa = *reinterpret_cast<const float4*>(wr + 24);
            const float4 wb = *reinterpret_cast<const float4*>(wr + 28);
            OROW_CHAIN(acc0, w, wa, wb, xa[0], xb[0], bb.w);
            OROW_CHAIN(acc1, w, wa, wb, xa[1], xb[1], bb.w);
            OROW_CHAIN(acc2, w, wa, wb, xa[2], xb[2], bb.w);
            OROW_CHAIN(acc3, w, wa, wb, xa[3], xb[3], bb.w);
        }

        // Stores: base + compile-time immediate only (cp*32 floats = 128B,
        // k step 737280 floats = 2949120B; both within STG's imm range).
        *reinterpret_cast<float4*>(base01 + cp * 32)                  = acc0;
        *reinterpret_cast<float4*>(base01 + OUT_K_STRIDE + cp * 32)   = acc1;
        *reinterpret_cast<float4*>(base23 + cp * 32)                  = acc2;
        *reinterpret_cast<float4*>(base23 + OUT_K_STRIDE + cp * 32)   = acc3;
    }
}

extern "C" void kernel_launch(void* const* d_in, const int* in_sizes, int n_in,
                              void* d_out, int out_size)
{
    const float* x    = (const float*)d_in[0];  // [B, R, I]
    const float* W    = (const float*)d_in[1];  // [1, R, C, O, I]
    const float* bias = (const float*)d_in[2];  // [O, 1]
    float* out = (float*)d_out;                 // [B, R, C, O, 1]

    cudaFuncSetAttribute(digitcaps_kernel,
                         cudaFuncAttributeMaxDynamicSharedMemorySize, SMEM_BYTES);

    dim3 block(128, 1, 1);
    dim3 grid(DC_R / RB, DC_B / BT, 1);   // (288, 32)
    digitcaps_kernel<<<grid, block, SMEM_BYTES>>>(x, W, bias, out);
}